// round 2
// baseline (speedup 1.0000x reference)
#include <cuda_runtime.h>
#include <cstdint>

#define TT 65536
#define KK 512
#define NEGV (-10000.0f)
#define CSZ 16            // cluster size (CTAs)
#define NPC (KK/CSZ)      // next-rows per CTA = 32
#define NTHR (NPC*8)      // 256 threads per CTA
#define LBT 256           // backtrack block length
#define BBT (TT/LBT)      // 256 backtrack blocks

// ---- device scratch (static; no runtime allocation) ----
__device__ unsigned short g_bp[(size_t)TT * KK];   // 64 MB backpointers
__device__ unsigned short g_maps[BBT * KK];        // per-block end->start maps
__device__ int            g_endtag[BBT];
__device__ int            g_best;

__device__ __forceinline__ uint32_t smem_u32(const void* p) {
    return (uint32_t)__cvta_generic_to_shared(p);
}
__device__ __forceinline__ void st_cluster_f32(uint32_t laddr, int r, float v) {
    uint32_t ra;
    asm("mapa.shared::cluster.u32 %0, %1, %2;" : "=r"(ra) : "r"(laddr), "r"(r));
    asm volatile("st.shared::cluster.f32 [%0], %1;" :: "r"(ra), "f"(v) : "memory");
}
__device__ __forceinline__ void cluster_sync_() {
    asm volatile("barrier.cluster.arrive.aligned;" ::: "memory");
    asm volatile("barrier.cluster.wait.aligned;" ::: "memory");
}
__device__ __forceinline__ uint32_t ctarank() {
    uint32_t r; asm("mov.u32 %0, %%cluster_ctarank;" : "=r"(r)); return r;
}

// ---- kernel 1: sequential forward pass (cluster-persistent) ----
__global__ void __launch_bounds__(NTHR, 1)
viterbi_fwd(const float* __restrict__ feats, const float* __restrict__ trans,
            float* __restrict__ dout, int idx0)
{
    __shared__ __align__(16) float fvbuf[2][KK];
    __shared__ float pval[8][NPC];
    __shared__ int   pidx[8][NPC];
    __shared__ float tv[NTHR];
    __shared__ int   ti[NTHR];

    const int tid = threadIdx.x;
    const int nl  = tid % NPC;          // local next row (lane)
    const int pc  = tid / NPC;          // prev chunk 0..7 (== warp id)
    const uint32_t rank = ctarank();
    const int n = (int)rank * NPC + nl; // global next row

    // transitions slice trans[n, pc*64 .. +64) -> registers
    float Tr[64];
    const float4* tp = (const float4*)(trans + (size_t)n * KK + pc * 64);
    #pragma unroll
    for (int q = 0; q < 16; q++) {
        float4 v = tp[q];
        Tr[4*q] = v.x; Tr[4*q+1] = v.y; Tr[4*q+2] = v.z; Tr[4*q+3] = v.w;
    }

    for (int i = tid; i < KK; i += NTHR) fvbuf[0][i] = (i == 0) ? 0.0f : NEGV;
    __syncthreads();
    cluster_sync_();

    const bool redw = (pc == 0);
    const uint32_t my_dst0 = smem_u32(&fvbuf[0][n]);
    const uint32_t my_dst1 = smem_u32(&fvbuf[1][n]);

    float ft = 0.0f;
    if (redw) ft = __ldg(feats + n);    // emission for t=0

    for (int t = 0; t < TT; ++t) {
        const int cur = t & 1;
        float ftn = 0.0f;
        if (redw && t + 1 < TT) ftn = __ldg(feats + (size_t)(t+1) * KK + n);

        // 64 candidates, 4 independent max-chains, first-index tie-break
        const float* fvp = &fvbuf[cur][pc * 64];
        float bv0 = -INFINITY, bv1 = -INFINITY, bv2 = -INFINITY, bv3 = -INFINITY;
        int   bi0 = 0, bi1 = 1, bi2 = 2, bi3 = 3;
        #pragma unroll
        for (int q = 0; q < 16; q++) {
            float4 f = *(const float4*)(fvp + 4*q);   // warp-broadcast LDS.128
            float s0 = f.x + Tr[4*q],   s1 = f.y + Tr[4*q+1];
            float s2 = f.z + Tr[4*q+2], s3 = f.w + Tr[4*q+3];
            if (s0 > bv0) { bv0 = s0; bi0 = 4*q; }
            if (s1 > bv1) { bv1 = s1; bi1 = 4*q+1; }
            if (s2 > bv2) { bv2 = s2; bi2 = 4*q+2; }
            if (s3 > bv3) { bv3 = s3; bi3 = 4*q+3; }
        }
        if (bv1 > bv0 || (bv1 == bv0 && bi1 < bi0)) { bv0 = bv1; bi0 = bi1; }
        if (bv3 > bv2 || (bv3 == bv2 && bi3 < bi2)) { bv2 = bv3; bi2 = bi3; }
        if (bv2 > bv0 || (bv2 == bv0 && bi2 < bi0)) { bv0 = bv2; bi0 = bi2; }

        pval[pc][nl] = bv0;
        pidx[pc][nl] = pc * 64 + bi0;
        __syncthreads();

        if (redw) {
            float v = pval[0][nl]; int i = pidx[0][nl];
            #pragma unroll
            for (int w = 1; w < 8; w++) {
                float v2 = pval[w][nl]; int i2 = pidx[w][nl];
                if (v2 > v || (v2 == v && i2 < i)) { v = v2; i = i2; }
            }
            g_bp[(size_t)t * KK + n] = (unsigned short)i;
            const float fvnew = v + ft;                 // exact: max + emission
            const uint32_t dst = cur ? my_dst0 : my_dst1;
            #pragma unroll
            for (int r = 0; r < CSZ; r++) st_cluster_f32(dst, r, fvnew);
        }
        ft = ftn;
        cluster_sync_();   // arrive=release orders the DSMEM pushes
    }

    // terminal = fv + trans[1,:]; first-index argmax (rank 0 only)
    if (rank == 0) {
        float v = -INFINITY; int i = 0;
        #pragma unroll
        for (int k = 0; k < KK / NTHR; k++) {
            const int p = tid * (KK / NTHR) + k;
            const float s = fvbuf[0][p] + trans[KK + p];
            if (s > v) { v = s; i = p; }
        }
        tv[tid] = v; ti[tid] = i;
        __syncthreads();
        if (tid == 0) {
            float bv = tv[0]; int bi = ti[0];
            for (int k = 1; k < NTHR; k++)
                if (tv[k] > bv || (tv[k] == bv && ti[k] < bi)) { bv = tv[k]; bi = ti[k]; }
            if (idx0 > 0) dout[0] = bv;
            g_best = bi;
        }
    }
}

// ---- kernel 2: per-block backtrack maps (parallel over blocks) ----
__global__ void bt_maps()
{
    __shared__ unsigned short rbuf[KK];
    const int b = blockIdx.x, tid = threadIdx.x;   // KK threads
    int x = tid;
    for (int s = LBT - 1; s >= 0; --s) {
        const size_t t = (size_t)b * LBT + s;
        rbuf[tid] = g_bp[t * KK + tid];
        __syncthreads();
        x = rbuf[x];
        __syncthreads();
    }
    g_maps[b * KK + tid] = (unsigned short)x;
}

// ---- kernel 3: compose block maps (serial, tiny) ----
__global__ void bt_compose()
{
    int e = g_best;
    g_endtag[BBT - 1] = e;
    for (int b = BBT - 1; b >= 1; --b) {
        e = g_maps[b * KK + e];
        g_endtag[b - 1] = e;
    }
}

// ---- kernel 4: fill best_path (parallel over blocks) ----
__global__ void bt_fill(float* __restrict__ dout, int idx0)
{
    const int b = blockIdx.x;
    int x = g_endtag[b];
    for (int s = LBT - 1; s >= 0; --s) {
        const size_t t = (size_t)b * LBT + s;
        dout[idx0 + t] = (float)x;
        x = g_bp[t * KK + x];
    }
}

extern "C" void kernel_launch(void* const* d_in, const int* in_sizes, int n_in,
                              void* d_out, int out_size)
{
    const float* feats = (const float*)d_in[0];
    const float* trans = (const float*)d_in[1];
    float* out = (float*)d_out;
    int idx0 = out_size - TT; if (idx0 < 0) idx0 = 0;

    cudaFuncSetAttribute(viterbi_fwd,
                         cudaFuncAttributeNonPortableClusterSizeAllowed, 1);
    cudaLaunchConfig_t cfg = {};
    cfg.gridDim  = dim3(CSZ, 1, 1);
    cfg.blockDim = dim3(NTHR, 1, 1);
    cfg.dynamicSmemBytes = 0;
    cfg.stream = 0;
    cudaLaunchAttribute at[1];
    at[0].id = cudaLaunchAttributeClusterDimension;
    at[0].val.clusterDim.x = CSZ;
    at[0].val.clusterDim.y = 1;
    at[0].val.clusterDim.z = 1;
    cfg.attrs = at; cfg.numAttrs = 1;
    cudaLaunchKernelEx(&cfg, viterbi_fwd, feats, trans, out, idx0);

    bt_maps<<<BBT, KK>>>();
    bt_compose<<<1, 1>>>();
    bt_fill<<<BBT, 1>>>(out, idx0);
}

// round 3
// speedup vs baseline: 1.1822x; 1.1822x over previous
#include <cuda_runtime.h>
#include <cstdint>

#define TT 65536
#define KK 512
#define NEGV (-10000.0f)
#define CSZ 16            // cluster CTAs
#define NPC 32            // next-rows per CTA
#define NTHR 256          // 8 warps
#define LBT 256
#define BBT (TT/LBT)
#define STEP_TX (KK*4)    // bytes arriving per CTA per step

// ---- static device scratch ----
__device__ unsigned short g_bp[(size_t)TT * KK];   // 64 MB backpointers
__device__ unsigned short g_maps[BBT * KK];
__device__ int            g_endtag[BBT];
__device__ int            g_best;

__device__ __forceinline__ uint32_t smem_u32(const void* p) {
    return (uint32_t)__cvta_generic_to_shared(p);
}
__device__ __forceinline__ uint32_t mapa_u32(uint32_t laddr, int r) {
    uint32_t ra;
    asm("mapa.shared::cluster.u32 %0, %1, %2;" : "=r"(ra) : "r"(laddr), "r"(r));
    return ra;
}
__device__ __forceinline__ void st_async_f32(uint32_t raddr, float v, uint32_t rmbar) {
    asm volatile(
        "st.async.weak.shared::cluster.mbarrier::complete_tx::bytes.b32 [%0], %1, [%2];"
        :: "r"(raddr), "r"(__float_as_uint(v)), "r"(rmbar) : "memory");
}
__device__ __forceinline__ void mbar_init(uint32_t a, uint32_t cnt) {
    asm volatile("mbarrier.init.shared.b64 [%0], %1;" :: "r"(a), "r"(cnt) : "memory");
}
__device__ __forceinline__ void mbar_expect_tx(uint32_t a, uint32_t bytes) {
    asm volatile("mbarrier.arrive.expect_tx.shared.b64 _, [%0], %1;"
                 :: "r"(a), "r"(bytes) : "memory");
}
__device__ __forceinline__ void mbar_wait(uint32_t a, uint32_t parity) {
    uint32_t done;
    asm volatile(
        "{\n\t.reg .pred p;\n\t"
        "mbarrier.try_wait.parity.acquire.cta.shared::cta.b64 p, [%1], %2;\n\t"
        "selp.b32 %0, 1, 0, p;\n\t}"
        : "=r"(done) : "r"(a), "r"(parity) : "memory");
    if (!done) {
        asm volatile(
            "{\n\t.reg .pred P1;\n\t"
            "W_%=:\n\t"
            "mbarrier.try_wait.parity.acquire.cta.shared::cta.b64 P1, [%0], %1, 0x989680;\n\t"
            "@P1 bra.uni D_%=;\n\t"
            "bra.uni W_%=;\n\t"
            "D_%=:\n\t}"
            :: "r"(a), "r"(parity) : "memory");
    }
}
__device__ __forceinline__ void cluster_sync_() {
    asm volatile("barrier.cluster.arrive.aligned;" ::: "memory");
    asm volatile("barrier.cluster.wait.aligned;" ::: "memory");
}
__device__ __forceinline__ uint32_t ctarank() {
    uint32_t r; asm("mov.u32 %0, %%cluster_ctarank;" : "=r"(r)); return r;
}

// ---- kernel 1: forward pass ----
__global__ void __launch_bounds__(NTHR, 1)
viterbi_fwd(const float* __restrict__ feats, const float* __restrict__ trans,
            float* __restrict__ dout, int idx0)
{
    __shared__ __align__(16) float fvbuf[2][KK];
    __shared__ __align__(8)  unsigned long long mbar[2];
    __shared__ float tv[NTHR];
    __shared__ int   ti[NTHR];

    const int tid   = threadIdx.x;
    const int lane  = tid & 31;
    const int w     = tid >> 5;        // warp 0..7: rows 4w..4w+3
    const int rl    = lane & 3;        // row within warp
    const int chunk = lane >> 2;       // prev chunk 0..7
    const uint32_t rank = ctarank();
    const int n = (int)rank * NPC + w * 4 + rl;   // my next-row

    // transitions slice trans[n, chunk*64 .. +64) -> registers
    float Tr[64];
    {
        const float4* tp = (const float4*)(trans + (size_t)n * KK + chunk * 64);
        #pragma unroll
        for (int q = 0; q < 16; q++) {
            float4 v = tp[q];
            Tr[4*q] = v.x; Tr[4*q+1] = v.y; Tr[4*q+2] = v.z; Tr[4*q+3] = v.w;
        }
    }

    // init: fv_{-1} lives in buf[1] (step t reads buf[(t+1)&1])
    for (int i2 = tid; i2 < KK; i2 += NTHR) fvbuf[1][i2] = (i2 == 0) ? 0.0f : NEGV;
    if (tid == 0) { mbar_init(smem_u32(&mbar[0]), 1); mbar_init(smem_u32(&mbar[1]), 1); }
    __syncthreads();
    cluster_sync_();     // peers' buffers + mbarriers ready

    const uint32_t mb0 = smem_u32(&mbar[0]);
    const uint32_t mb1 = smem_u32(&mbar[1]);
    uint32_t rmb0[CSZ], rmb1[CSZ];
    #pragma unroll
    for (int r = 0; r < CSZ; r++) { rmb0[r] = mapa_u32(mb0, r); rmb1[r] = mapa_u32(mb1, r); }
    const uint32_t a_row0 = smem_u32(&fvbuf[0][n]);
    const uint32_t a_row1 = smem_u32(&fvbuf[1][n]);

    float ft = (chunk == 0) ? __ldg(feats + n) : 0.0f;   // emission for t=0

    for (int t = 0; t < TT; ++t) {
        if (tid == 0) mbar_expect_tx((t & 1) ? mb1 : mb0, STEP_TX);

        float ftn = 0.0f;
        if (chunk == 0) {
            int tn = (t + 1 < TT) ? t + 1 : t;
            ftn = __ldg(feats + (size_t)tn * KK + n);
        }

        // 64 candidates, 4 strided chains, exact first-index tie-break
        const float* fvp = &fvbuf[(t + 1) & 1][chunk * 64];
        float bv0 = -INFINITY, bv1 = -INFINITY, bv2 = -INFINITY, bv3 = -INFINITY;
        int   bj0 = 0, bj1 = 0, bj2 = 0, bj3 = 0;
        #pragma unroll
        for (int q = 0; q < 16; q++) {
            float4 f = *(const float4*)(fvp + 4*q);
            float s0 = f.x + Tr[4*q],   s1 = f.y + Tr[4*q+1];
            float s2 = f.z + Tr[4*q+2], s3 = f.w + Tr[4*q+3];
            bool g0 = s0 > bv0; bv0 = g0 ? s0 : bv0; bj0 = g0 ? 4*q : bj0;
            bool g1 = s1 > bv1; bv1 = g1 ? s1 : bv1; bj1 = g1 ? 4*q : bj1;
            bool g2 = s2 > bv2; bv2 = g2 ? s2 : bv2; bj2 = g2 ? 4*q : bj2;
            bool g3 = s3 > bv3; bv3 = g3 ? s3 : bv3; bj3 = g3 ? 4*q : bj3;
        }
        int i0 = chunk*64 + bj0, i1 = chunk*64 + bj1 + 1;
        int i2 = chunk*64 + bj2 + 2, i3 = chunk*64 + bj3 + 3;
        if (bv1 > bv0 || (bv1 == bv0 && i1 < i0)) { bv0 = bv1; i0 = i1; }
        if (bv3 > bv2 || (bv3 == bv2 && i3 < i2)) { bv2 = bv3; i2 = i3; }
        if (bv2 > bv0 || (bv2 == bv0 && i2 < i0)) { bv0 = bv2; i0 = i2; }

        // warp reduce over chunk bits (lane xor 4,8,16), first-index tie-break
        float v = bv0; int i = i0;
        #pragma unroll
        for (int d = 4; d <= 16; d <<= 1) {
            float vo = __shfl_xor_sync(0xffffffffu, v, d);
            int   io = __shfl_xor_sync(0xffffffffu, i, d);
            if (vo > v || (vo == v && io < i)) { v = vo; i = io; }
        }

        if (chunk == 0) {            // lanes 0-3 own rows 4w..4w+3
            g_bp[(size_t)t * KK + n] = (unsigned short)i;
            const float fvnew = v + ft;                 // exact: max + emission
            const uint32_t al = (t & 1) ? a_row1 : a_row0;
            if (t & 1) {
                #pragma unroll
                for (int r = 0; r < CSZ; r++) st_async_f32(mapa_u32(al, r), fvnew, rmb1[r]);
            } else {
                #pragma unroll
                for (int r = 0; r < CSZ; r++) st_async_f32(mapa_u32(al, r), fvnew, rmb0[r]);
            }
        }
        ft = ftn;
        mbar_wait((t & 1) ? mb1 : mb0, (t >> 1) & 1);
    }

    // terminal = fv + trans[1,:]; first-index argmax (rank 0)
    if (rank == 0) {
        float v = -INFINITY; int i = 0;
        #pragma unroll
        for (int k = 0; k < KK / NTHR; k++) {
            const int p = tid * (KK / NTHR) + k;
            const float s = fvbuf[1][p] + trans[KK + p];
            if (s > v) { v = s; i = p; }
        }
        tv[tid] = v; ti[tid] = i;
        __syncthreads();
        if (tid == 0) {
            float bv = tv[0]; int bi = ti[0];
            for (int k = 1; k < NTHR; k++)
                if (tv[k] > bv || (tv[k] == bv && ti[k] < bi)) { bv = tv[k]; bi = ti[k]; }
            if (idx0 > 0) dout[0] = bv;
            g_best = bi;
        }
    }
    cluster_sync_();   // keep cluster alive until all remote traffic done
}

// ---- kernel 2: per-block backtrack maps ----
__global__ void bt_maps()
{
    __shared__ unsigned short rbuf[KK];
    const int b = blockIdx.x, tid = threadIdx.x;   // KK threads
    int x = tid;
    for (int s = LBT - 1; s >= 0; --s) {
        const size_t t = (size_t)b * LBT + s;
        rbuf[tid] = g_bp[t * KK + tid];
        __syncthreads();
        x = rbuf[x];
        __syncthreads();
    }
    g_maps[b * KK + tid] = (unsigned short)x;
}

// ---- kernel 3: compose block maps ----
__global__ void bt_compose()
{
    int e = g_best;
    g_endtag[BBT - 1] = e;
    for (int b = BBT - 1; b >= 1; --b) {
        e = g_maps[b * KK + e];
        g_endtag[b - 1] = e;
    }
}

// ---- kernel 4: fill best_path ----
__global__ void bt_fill(float* __restrict__ dout, int idx0)
{
    const int b = blockIdx.x;
    int x = g_endtag[b];
    for (int s = LBT - 1; s >= 0; --s) {
        const size_t t = (size_t)b * LBT + s;
        dout[idx0 + t] = (float)x;
        x = g_bp[t * KK + x];
    }
}

extern "C" void kernel_launch(void* const* d_in, const int* in_sizes, int n_in,
                              void* d_out, int out_size)
{
    const float* feats = (const float*)d_in[0];
    const float* trans = (const float*)d_in[1];
    float* out = (float*)d_out;
    int idx0 = out_size - TT; if (idx0 < 0) idx0 = 0;

    cudaFuncSetAttribute(viterbi_fwd,
                         cudaFuncAttributeNonPortableClusterSizeAllowed, 1);
    cudaLaunchConfig_t cfg = {};
    cfg.gridDim  = dim3(CSZ, 1, 1);
    cfg.blockDim = dim3(NTHR, 1, 1);
    cfg.dynamicSmemBytes = 0;
    cfg.stream = 0;
    cudaLaunchAttribute at[1];
    at[0].id = cudaLaunchAttributeClusterDimension;
    at[0].val.clusterDim.x = CSZ;
    at[0].val.clusterDim.y = 1;
    at[0].val.clusterDim.z = 1;
    cfg.attrs = at; cfg.numAttrs = 1;
    cudaLaunchKernelEx(&cfg, viterbi_fwd, feats, trans, out, idx0);

    bt_maps<<<BBT, KK>>>();
    bt_compose<<<1, 1>>>();
    bt_fill<<<BBT, 1>>>(out, idx0);
}